// round 1
// baseline (speedup 1.0000x reference)
#include <cuda_runtime.h>

#define HH 192
#define WW 192
#define NPIX (HH*WW)        // 36864
#define CIN 128
#define DK 256
#define NHEAD 8
#define DH 32               // channels per head
#define TEMPER_INV (1.0f/16.0f)

// Scratch (no cudaMalloc allowed): v projection + per-head qk dot
__device__ float V_scr[DK * NPIX];      // [256][36864]
__device__ float S_scr[NHEAD * NPIX];   // [8][36864]

typedef unsigned long long u64;

__device__ __forceinline__ u64 pk2(float v) {
    u64 r; asm("mov.b64 %0, {%1, %2};" : "=l"(r) : "f"(v), "f"(v)); return r;
}
__device__ __forceinline__ void fma2(u64 &d, u64 a, u64 b) {
    asm("fma.rn.f32x2 %0, %1, %2, %0;" : "+l"(d) : "l"(a), "l"(b));
}

// ---------------------------------------------------------------------------
// Pass 1: per 128-pixel tile, compute q,k,v for all 256 channels.
// Warp g (== head g) handles channels [32g, 32g+32). Lane handles 4 pixels.
// q,k reduced on the fly into per-head dot S; v written to scratch.
// ---------------------------------------------------------------------------
extern __shared__ float xs[];   // [128][128] = 64 KB (dynamic)

__global__ void __launch_bounds__(256, 2) proj_kernel(
    const float* __restrict__ x,
    const float* __restrict__ wq,
    const float* __restrict__ wk,
    const float* __restrict__ wv)
{
    const int base = blockIdx.x * 128;
    const int t = threadIdx.x;

    // Load x tile [128c][128px], coalesced float4
    const float4* xg = (const float4*)x;
    float4* xs4 = (float4*)xs;
    #pragma unroll
    for (int i = 0; i < 16; i++) {
        int idx = t + i * 256;            // 0..4095
        int c  = idx >> 5;                // 32 float4 per row
        int po = idx & 31;
        xs4[idx] = xg[c * (NPIX/4) + (base >> 2) + po];
    }
    __syncthreads();

    const int g    = t >> 5;   // warp index == head index
    const int lane = t & 31;
    const int p0   = lane * 4;

    u64 sd0 = 0ULL, sd1 = 0ULL;   // per-head qk dot, 2 pixel-pairs

    for (int dd = 0; dd < DH; dd++) {
        const int d = g * DH + dd;
        const float4* wq4 = (const float4*)(wq + d * CIN);
        const float4* wk4 = (const float4*)(wk + d * CIN);
        const float4* wv4 = (const float4*)(wv + d * CIN);

        u64 qa0 = 0, qa1 = 0, ka0 = 0, ka1 = 0, va0 = 0, va1 = 0;

        #pragma unroll
        for (int kk = 0; kk < CIN/4; kk++) {
            float4 aq = __ldg(wq4 + kk);
            float4 ak = __ldg(wk4 + kk);
            float4 av = __ldg(wv4 + kk);
            #define STEP(QC, KC, VC, KIDX) { \
                ulonglong2 xv = *(const ulonglong2*)(xs + (KIDX)*128 + p0); \
                u64 wq2 = pk2(QC); u64 wk2 = pk2(KC); u64 wv2 = pk2(VC);   \
                fma2(qa0, wq2, xv.x); fma2(qa1, wq2, xv.y);                \
                fma2(ka0, wk2, xv.x); fma2(ka1, wk2, xv.y);                \
                fma2(va0, wv2, xv.x); fma2(va1, wv2, xv.y); }
            STEP(aq.x, ak.x, av.x, kk*4 + 0)
            STEP(aq.y, ak.y, av.y, kk*4 + 1)
            STEP(aq.z, ak.z, av.z, kk*4 + 2)
            STEP(aq.w, ak.w, av.w, kk*4 + 3)
            #undef STEP
        }

        // per-pixel q*k into head dot (elementwise pair fma)
        fma2(sd0, qa0, ka0);
        fma2(sd1, qa1, ka1);

        // store v row (coalesced 16B per lane)
        ulonglong2 vv; vv.x = va0; vv.y = va1;
        *(ulonglong2*)&V_scr[d * NPIX + base + p0] = vv;
    }

    ulonglong2 sv; sv.x = sd0; sv.y = sd1;
    *(ulonglong2*)&S_scr[g * NPIX + base + p0] = sv;
}

// ---------------------------------------------------------------------------
// Pass 2: per (head, 16x16 pixel tile): softmax over 9 neighbor logits,
// then 9-tap weighted sum of v for the head's 32 channels.
// OOB neighbors: logit 0 and v 0 (matches zero-padded stretch).
// ---------------------------------------------------------------------------
__global__ void __launch_bounds__(256) attn_kernel(float* __restrict__ out)
{
    __shared__ float vs[DH][18][20];
    __shared__ float ss[18][20];

    const int h  = blockIdx.z;
    const int bx = blockIdx.x * 16;
    const int by = blockIdx.y * 16;
    const int t  = threadIdx.x;

    // load s halo (18x18)
    for (int i = t; i < 18*18; i += 256) {
        int yy = i / 18, xx = i - yy * 18;
        int gy = by + yy - 1, gx = bx + xx - 1;
        float v = 0.f;
        if (gy >= 0 && gy < HH && gx >= 0 && gx < WW)
            v = S_scr[h * NPIX + gy * WW + gx];
        ss[yy][xx] = v;
    }
    // load v halo (32 x 18 x 18)
    for (int i = t; i < DH*18*18; i += 256) {
        int c = i / 324; int rem = i - c * 324;
        int yy = rem / 18, xx = rem - yy * 18;
        int gy = by + yy - 1, gx = bx + xx - 1;
        float v = 0.f;
        if (gy >= 0 && gy < HH && gx >= 0 && gx < WW)
            v = V_scr[(h * DH + c) * NPIX + gy * WW + gx];
        vs[c][yy][xx] = v;
    }
    __syncthreads();

    const int lx = t & 15, ly = t >> 4;
    const int cy = ly + 1, cx = lx + 1;

    float lg[9];
    #pragma unroll
    for (int s = 0; s < 9; s++) {
        int dy = s / 3 - 1, dx = s % 3 - 1;
        lg[s] = ss[cy + dy][cx + dx] * TEMPER_INV;
    }
    float m = lg[0];
    #pragma unroll
    for (int s = 1; s < 9; s++) m = fmaxf(m, lg[s]);
    float e[9], den = 0.f;
    #pragma unroll
    for (int s = 0; s < 9; s++) { e[s] = __expf(lg[s] - m); den += e[s]; }
    float inv = 1.0f / den;
    #pragma unroll
    for (int s = 0; s < 9; s++) e[s] *= inv;

    const int gy = by + ly, gx = bx + lx;
    float* op = out + h * DH * NPIX + gy * WW + gx;
    #pragma unroll
    for (int c = 0; c < DH; c++) {
        float acc = 0.f;
        #pragma unroll
        for (int s = 0; s < 9; s++) {
            int dy = s / 3 - 1, dx = s % 3 - 1;
            acc += e[s] * vs[c][cy + dy][cx + dx];
        }
        op[c * NPIX] = acc;
    }
}

// ---------------------------------------------------------------------------
extern "C" void kernel_launch(void* const* d_in, const int* in_sizes, int n_in,
                              void* d_out, int out_size)
{
    const float* x  = (const float*)d_in[0];
    const float* wq = (const float*)d_in[1];
    const float* wk = (const float*)d_in[2];
    const float* wv = (const float*)d_in[3];
    float* out = (float*)d_out;

    // 64 KB dynamic smem for the x tile (idempotent; host-side attr, capture-safe)
    cudaFuncSetAttribute(proj_kernel, cudaFuncAttributeMaxDynamicSharedMemorySize, 65536);

    proj_kernel<<<NPIX / 128, 256, 65536>>>(x, wq, wk, wv);

    dim3 g2(WW / 16, HH / 16, NHEAD);
    attn_kernel<<<g2, 256>>>(out);
}

// round 2
// speedup vs baseline: 1.1680x; 1.1680x over previous
#include <cuda_runtime.h>

#define HH 192
#define WW 192
#define NPIX (HH*WW)        // 36864
#define CIN 128
#define DK 256
#define NHEAD 8
#define DH 32
#define TEMPER_INV (1.0f/16.0f)

typedef unsigned long long u64;

// Scratch (no cudaMalloc allowed)
__device__ float V_scr[DK * NPIX];        // [256][36864]
__device__ float S_scr[NHEAD * NPIX];     // [8][36864]
__device__ u64   WQK[DK * CIN];           // (wq[d][c], wk[d][c])
__device__ u64   WVV[(DK/2) * CIN];       // (wv[2i][c], wv[2i+1][c])

__device__ __forceinline__ u64 pk2(float a, float b) {
    u64 r; asm("mov.b64 %0, {%1, %2};" : "=l"(r) : "f"(a), "f"(b)); return r;
}
__device__ __forceinline__ void unpk2(u64 v, float &a, float &b) {
    asm("mov.b64 {%0, %1}, %2;" : "=f"(a), "=f"(b) : "l"(v));
}
__device__ __forceinline__ void fma2(u64 &d, u64 a, u64 b) {
    asm("fma.rn.f32x2 %0, %1, %2, %0;" : "+l"(d) : "l"(a), "l"(b));
}

// ---------------------------------------------------------------------------
// Prep: pack weights into duplicate-free pair layouts (runs every launch,
// deterministic, ~3us)
// ---------------------------------------------------------------------------
__global__ void pack_w_kernel(const float* __restrict__ wq,
                              const float* __restrict__ wk,
                              const float* __restrict__ wv)
{
    int i = blockIdx.x * 256 + threadIdx.x;   // grid covers DK*CIN = 32768
    if (i < DK * CIN)
        WQK[i] = pk2(wq[i], wk[i]);
    if (i < (DK/2) * CIN) {
        int d2 = i / CIN, c = i - d2 * CIN;
        WVV[i] = pk2(wv[(2*d2) * CIN + c], wv[(2*d2+1) * CIN + c]);
    }
}

// ---------------------------------------------------------------------------
// Pass 1: projections + per-head qk dot.
// Block: 128 pixels, 256 threads (8 warps). Warp g = head g (32 channels).
// smem: x tile pre-DUPLICATED: xsd[c][2p..2p+1] = x[c][p]  (128 x 256 floats)
// Lane handles pixels {lane, lane+32, lane+64, lane+96}; register-blocks
// 4 channels. qk accumulators hold (q_d[p], k_d[p]) pairs via WQK;
// v accumulators hold (v_d0[p], v_d1[p]) pairs via WVV. Zero packing movs
// in the hot loop.
// ---------------------------------------------------------------------------
extern __shared__ float xsd[];   // 128 * 256 floats = 128 KB dynamic

__global__ void __launch_bounds__(256, 1) proj_kernel(const float* __restrict__ x)
{
    const int base = blockIdx.x * 128;
    const int t = threadIdx.x;

    // Fill duplicated tile
    const float4* xg = (const float4*)x;
    #pragma unroll
    for (int i = 0; i < 16; i++) {
        int idx = t + i * 256;          // 0..4095 float4s
        int c  = idx >> 5;              // 32 float4 per channel row
        int po = idx & 31;
        float4 f = xg[c * (NPIX/4) + (base >> 2) + po];
        float4* dst = (float4*)(xsd + c * 256 + po * 8);
        dst[0] = make_float4(f.x, f.x, f.y, f.y);
        dst[1] = make_float4(f.z, f.z, f.w, f.w);
    }
    __syncthreads();

    const int g = t >> 5, lane = t & 31;
    float sacc[4] = {0.f, 0.f, 0.f, 0.f};

    for (int j = 0; j < 8; j++) {
        const int d0 = g * DH + j * 4;
        const u64* w0  = &WQK[(d0 + 0) * CIN];
        const u64* w1  = &WQK[(d0 + 1) * CIN];
        const u64* w2  = &WQK[(d0 + 2) * CIN];
        const u64* w3  = &WQK[(d0 + 3) * CIN];
        const u64* wv0 = &WVV[((d0 >> 1) + 0) * CIN];
        const u64* wv1 = &WVV[((d0 >> 1) + 1) * CIN];

        u64 qk[4][4]; u64 vv[2][4];
        #pragma unroll
        for (int i = 0; i < 4; i++) {
            qk[0][i] = 0; qk[1][i] = 0; qk[2][i] = 0; qk[3][i] = 0;
            vv[0][i] = 0; vv[1][i] = 0;
        }

        #pragma unroll 2
        for (int c = 0; c < CIN; c += 2) {
            ulonglong2 a0 = *(const ulonglong2*)(w0 + c);
            ulonglong2 a1 = *(const ulonglong2*)(w1 + c);
            ulonglong2 a2 = *(const ulonglong2*)(w2 + c);
            ulonglong2 a3 = *(const ulonglong2*)(w3 + c);
            ulonglong2 b0 = *(const ulonglong2*)(wv0 + c);
            ulonglong2 b1 = *(const ulonglong2*)(wv1 + c);

            u64 xa[4], xb[4];
            #pragma unroll
            for (int i = 0; i < 4; i++) {
                xa[i] = *(const u64*)(xsd + c * 256 + 2 * lane + 64 * i);
                xb[i] = *(const u64*)(xsd + (c + 1) * 256 + 2 * lane + 64 * i);
            }
            #pragma unroll
            for (int i = 0; i < 4; i++) {
                fma2(qk[0][i], a0.x, xa[i]); fma2(qk[0][i], a0.y, xb[i]);
                fma2(qk[1][i], a1.x, xa[i]); fma2(qk[1][i], a1.y, xb[i]);
                fma2(qk[2][i], a2.x, xa[i]); fma2(qk[2][i], a2.y, xb[i]);
                fma2(qk[3][i], a3.x, xa[i]); fma2(qk[3][i], a3.y, xb[i]);
                fma2(vv[0][i], b0.x, xa[i]); fma2(vv[0][i], b0.y, xb[i]);
                fma2(vv[1][i], b1.x, xa[i]); fma2(vv[1][i], b1.y, xb[i]);
            }
        }

        // Reduce qk pairs into head dot; store v (coalesced: lane-stride 4B)
        #pragma unroll
        for (int i = 0; i < 4; i++) {
            int p = base + lane + 32 * i;
            float q0,k0,q1,k1,q2,k2,q3,k3;
            unpk2(qk[0][i], q0, k0); unpk2(qk[1][i], q1, k1);
            unpk2(qk[2][i], q2, k2); unpk2(qk[3][i], q3, k3);
            sacc[i] += q0*k0 + q1*k1 + q2*k2 + q3*k3;
            float v0,v1,v2,v3;
            unpk2(vv[0][i], v0, v1); unpk2(vv[1][i], v2, v3);
            V_scr[(d0+0) * NPIX + p] = v0;
            V_scr[(d0+1) * NPIX + p] = v1;
            V_scr[(d0+2) * NPIX + p] = v2;
            V_scr[(d0+3) * NPIX + p] = v3;
        }
    }
    #pragma unroll
    for (int i = 0; i < 4; i++)
        S_scr[g * NPIX + base + lane + 32 * i] = sacc[i];
}

// ---------------------------------------------------------------------------
// Pass 2: softmax over 9 region slots + 9-tap weighted v sum.
// Channel-contiguous smem layout vs[y][x][36] -> float4 taps, conflict-free.
// ---------------------------------------------------------------------------
__global__ void __launch_bounds__(256) attn_kernel(float* __restrict__ out)
{
    __shared__ float vs[18 * 18 * 36];   // 46656 floats? no: bytes = 46656*4... 
    // NOTE: 18*18*36 floats = 11664 floats = 46656 bytes
    __shared__ float ss[18][18];

    const int h  = blockIdx.z;
    const int bx = blockIdx.x * 16;
    const int by = blockIdx.y * 16;
    const int t  = threadIdx.x;

    for (int i = t; i < 18 * 18; i += 256) {
        int yy = i / 18, xx = i - yy * 18;
        int gy = by + yy - 1, gx = bx + xx - 1;
        float v = 0.f;
        if ((unsigned)gy < HH && (unsigned)gx < WW)
            v = S_scr[h * NPIX + gy * WW + gx];
        ss[yy][xx] = v;
    }
    for (int i = t; i < DH * 18 * 18; i += 256) {
        int xx = i % 18; int r = i / 18; int yy = r % 18; int c = r / 18;
        int gy = by + yy - 1, gx = bx + xx - 1;
        float v = 0.f;
        if ((unsigned)gy < HH && (unsigned)gx < WW)
            v = V_scr[(h * DH + c) * NPIX + gy * WW + gx];
        vs[(yy * 18 + xx) * 36 + c] = v;
    }
    __syncthreads();

    const int lx = t & 15, ly = t >> 4;
    const int cy = ly + 1, cx = lx + 1;

    float lg[9];
    #pragma unroll
    for (int s = 0; s < 9; s++) {
        int dy = s / 3 - 1, dx = s % 3 - 1;
        lg[s] = ss[cy + dy][cx + dx] * TEMPER_INV;
    }
    float m = lg[0];
    #pragma unroll
    for (int s = 1; s < 9; s++) m = fmaxf(m, lg[s]);
    float e[9], den = 0.f;
    #pragma unroll
    for (int s = 0; s < 9; s++) { e[s] = __expf(lg[s] - m); den += e[s]; }
    float inv = 1.0f / den;
    #pragma unroll
    for (int s = 0; s < 9; s++) e[s] *= inv;

    float* op = out + (h * DH) * NPIX + (by + ly) * WW + (bx + lx);
    #pragma unroll
    for (int cg = 0; cg < 8; cg++) {
        float4 acc = make_float4(0.f, 0.f, 0.f, 0.f);
        #pragma unroll
        for (int s = 0; s < 9; s++) {
            int dy = s / 3 - 1, dx = s % 3 - 1;
            const float4 tv = *(const float4*)&vs[((cy+dy) * 18 + (cx+dx)) * 36 + cg * 4];
            acc.x += e[s] * tv.x; acc.y += e[s] * tv.y;
            acc.z += e[s] * tv.z; acc.w += e[s] * tv.w;
        }
        op[(cg*4 + 0) * NPIX] = acc.x;
        op[(cg*4 + 1) * NPIX] = acc.y;
        op[(cg*4 + 2) * NPIX] = acc.z;
        op[(cg*4 + 3) * NPIX] = acc.w;
    }
}

// ---------------------------------------------------------------------------
extern "C" void kernel_launch(void* const* d_in, const int* in_sizes, int n_in,
                              void* d_out, int out_size)
{
    const float* x  = (const float*)d_in[0];
    const float* wq = (const float*)d_in[1];
    const float* wk = (const float*)d_in[2];
    const float* wv = (const float*)d_in[3];
    float* out = (float*)d_out;

    cudaFuncSetAttribute(proj_kernel, cudaFuncAttributeMaxDynamicSharedMemorySize, 131072);

    pack_w_kernel<<<(DK * CIN + 255) / 256, 256>>>(wq, wk, wv);
    proj_kernel<<<NPIX / 128, 256, 131072>>>(x);

    dim3 g2(WW / 16, HH / 16, NHEAD);
    attn_kernel<<<g2, 256>>>(out);
}

// round 10
// speedup vs baseline: 2.5232x; 2.1602x over previous
#include <cuda_runtime.h>
#include <cuda_bf16.h>
#include <cstdint>

#define HH 192
#define WW 192
#define NPIX (HH*WW)        // 36864
#define CIN 128
#define NHEAD 8
#define DH 32
#define TEMPER_INV (1.0f/16.0f)

// ---------------- global scratch (no cudaMalloc allowed) ----------------
__device__ float V_scrT[(size_t)NPIX * 256];               // [pixel][256 ch]
__device__ float S_scr[NHEAD * NPIX];                      // [head][pixel]
__device__ __align__(16) __nv_bfloat16 Whi[768 * 128];     // rows: q(0-255) k(256-511) v(512-767)
__device__ __align__(16) __nv_bfloat16 Wlo[768 * 128];

// ---------------- smem layout (bytes) ----------------
#define ROWB 272                       // 136 halves per row (128 data + 8 pad)
#define X_H  0
#define X_L  34816                     // 128*272
#define WB0  69632
#define WB1  139264
#define SMEM_SZ 208896                 // WB1 + 69632
#define WPLANE 34816                   // lo-plane offset inside a W buffer

// ---------------- helpers ----------------
__device__ __forceinline__ uint32_t smem_u32(const void* p) {
    uint32_t a;
    asm("{ .reg .u64 t; cvta.to.shared.u64 t, %1; cvt.u32.u64 %0, t; }" : "=r"(a) : "l"(p));
    return a;
}
__device__ __forceinline__ void ldsm4(uint32_t r[4], uint32_t addr) {
    asm volatile("ldmatrix.sync.aligned.m8n8.x4.shared.b16 {%0,%1,%2,%3}, [%4];"
        : "=r"(r[0]), "=r"(r[1]), "=r"(r[2]), "=r"(r[3]) : "r"(addr));
}
__device__ __forceinline__ void mma16816(float d[4], const uint32_t a[4], uint32_t b0, uint32_t b1) {
    asm volatile("mma.sync.aligned.m16n8k16.row.col.f32.bf16.bf16.f32 "
        "{%0,%1,%2,%3},{%4,%5,%6,%7},{%8,%9},{%0,%1,%2,%3};"
        : "+f"(d[0]), "+f"(d[1]), "+f"(d[2]), "+f"(d[3])
        : "r"(a[0]), "r"(a[1]), "r"(a[2]), "r"(a[3]), "r"(b0), "r"(b1));
}

// ---------------------------------------------------------------------------
// Weight pack: bf16 hi/lo planes, rows = stacked channels q|k|v, k-contiguous
// ---------------------------------------------------------------------------
__global__ void pack_w_kernel(const float* __restrict__ wq,
                              const float* __restrict__ wk,
                              const float* __restrict__ wv)
{
    int i = blockIdx.x * 256 + threadIdx.x;       // 768*128 = 98304
    if (i >= 768 * 128) return;
    int ch = i >> 7, c = i & 127;
    float w;
    if (ch < 256)      w = wq[ch * CIN + c];
    else if (ch < 512) w = wk[(ch - 256) * CIN + c];
    else               w = wv[(ch - 512) * CIN + c];
    __nv_bfloat16 h = __float2bfloat16(w);
    __nv_bfloat16 l = __float2bfloat16(w - __bfloat162float(h));
    Whi[i] = h;
    Wlo[i] = l;
}

// ---------------------------------------------------------------------------
// Pass 1: HMMA projections. CTA = 128 pixels, 256 threads (8 warps x 16 pix).
// ---------------------------------------------------------------------------
__device__ __forceinline__ void copyW(char* smem, int dstoff, int ch0, int t) {
    const float4* hs = (const float4*)Whi;
    const float4* ls = (const float4*)Wlo;
    #pragma unroll
    for (int i = 0; i < 16; i++) {
        int idx = t + i * 256;                // 0..4095 float4
        int plane = idx >> 11;
        int r  = (idx >> 4) & 127;
        int cc = idx & 15;
        const float4* src = plane ? ls : hs;
        float4 v = src[(ch0 + r) * 16 + cc];
        *(float4*)(smem + dstoff + plane * WPLANE + r * ROWB + cc * 16) = v;
    }
}

// compute one 16x8 output tile (3-pass bf16 split) for n-tile nt from W buffer
#define COMPUTE_TILE(D, bufoff, nt) do {                                        \
    uint32_t bw[16];                                                            \
    uint32_t bb = sb + (bufoff) + ((nt) * 8 + lr) * ROWB + mi * 16;             \
    _Pragma("unroll")                                                           \
    for (int k2 = 0; k2 < 4; k2++) ldsm4(&bw[4 * k2], bb + k2 * 64);            \
    _Pragma("unroll")                                                           \
    for (int kt = 0; kt < 8; kt++) mma16816(D, &ah[4 * kt], bw[2 * kt], bw[2 * kt + 1]); \
    _Pragma("unroll")                                                           \
    for (int kt = 0; kt < 8; kt++) mma16816(D, &al[4 * kt], bw[2 * kt], bw[2 * kt + 1]); \
    _Pragma("unroll")                                                           \
    for (int k2 = 0; k2 < 4; k2++) ldsm4(&bw[4 * k2], bb + WPLANE + k2 * 64);   \
    _Pragma("unroll")                                                           \
    for (int kt = 0; kt < 8; kt++) mma16816(D, &ah[4 * kt], bw[2 * kt], bw[2 * kt + 1]); \
} while (0)

__global__ void __launch_bounds__(256, 1) proj_mma_kernel(const float* __restrict__ x)
{
    extern __shared__ char smem[];
    const uint32_t sb = smem_u32(smem);
    const int t = threadIdx.x;
    const int wid = t >> 5, lane = t & 31;
    const int base = blockIdx.x * 128;

    // ---- x tile: load, bf16 hi/lo split, store transposed [pix][k] ----
    #pragma unroll 4
    for (int i = 0; i < 64; i++) {
        int idx = t + i * 256;            // 0..16383
        int c = idx >> 7, p = idx & 127;
        float f = x[c * NPIX + base + p];
        __nv_bfloat16 h = __float2bfloat16(f);
        __nv_bfloat16 l = __float2bfloat16(f - __bfloat162float(h));
        *(unsigned short*)(smem + X_H + p * ROWB + c * 2) = __bfloat16_as_ushort(h);
        *(unsigned short*)(smem + X_L + p * ROWB + c * 2) = __bfloat16_as_ushort(l);
    }
    __syncthreads();

    // ---- A fragments (held in registers for the whole kernel) ----
    const int mi = lane >> 3, lr = lane & 7;
    const int rowA = wid * 16 + ((mi & 1) << 3) + lr;
    const uint32_t aoff = rowA * ROWB + ((mi >> 1) << 4);
    uint32_t ah[32], al[32];
    #pragma unroll
    for (int kt = 0; kt < 8; kt++) ldsm4(&ah[4 * kt], sb + X_H + aoff + kt * 32);
    #pragma unroll
    for (int kt = 0; kt < 8; kt++) ldsm4(&al[4 * kt], sb + X_L + aoff + kt * 32);
    __syncthreads();          // x region re-readable; nothing overwrites it anyway

    const int g = lane >> 2;                 // row within warp tile
    const int cq = lane & 3;                 // col quad index
    const int p0 = base + wid * 16 + g;

    // ---- qk phases: heads 0-3 then 4-7 ----
    #pragma unroll 1
    for (int h2 = 0; h2 < 2; h2++) {
        copyW(smem, WB0, h2 * 128, t);           // q chunk
        copyW(smem, WB1, 256 + h2 * 128, t);     // k chunk
        __syncthreads();

        float sp0 = 0.f, sp1 = 0.f;
        #pragma unroll 1
        for (int nt = 0; nt < 16; nt++) {
            float qd[4] = {0.f, 0.f, 0.f, 0.f};
            float kd[4] = {0.f, 0.f, 0.f, 0.f};
            COMPUTE_TILE(qd, WB0, nt);
            COMPUTE_TILE(kd, WB1, nt);
            sp0 += qd[0] * kd[0] + qd[1] * kd[1];
            sp1 += qd[2] * kd[2] + qd[3] * kd[3];
            if ((nt & 3) == 3) {
                float v0 = sp0, v1 = sp1;
                v0 += __shfl_xor_sync(0xffffffffu, v0, 1);
                v0 += __shfl_xor_sync(0xffffffffu, v0, 2);
                v1 += __shfl_xor_sync(0xffffffffu, v1, 1);
                v1 += __shfl_xor_sync(0xffffffffu, v1, 2);
                if (cq == 0) {
                    int head = h2 * 4 + (nt >> 2);
                    S_scr[head * NPIX + p0] = v0;
                    S_scr[head * NPIX + p0 + 8] = v1;
                }
                sp0 = 0.f; sp1 = 0.f;
            }
        }
        __syncthreads();
    }

    // ---- v phase: channels 0-255 (global rows 512-767) ----
    copyW(smem, WB0, 512, t);
    copyW(smem, WB1, 640, t);
    __syncthreads();
    #pragma unroll 1
    for (int vc = 0; vc < 2; vc++) {
        const int bufoff = vc ? WB1 : WB0;
        #pragma unroll 1
        for (int nt = 0; nt < 16; nt++) {
            float D[4] = {0.f, 0.f, 0.f, 0.f};
            COMPUTE_TILE(D, bufoff, nt);
            int ch = vc * 128 + nt * 8 + (cq << 1);
            float2 lo; lo.x = D[0]; lo.y = D[1];
            float2 hi; hi.x = D[2]; hi.y = D[3];
            *(float2*)&V_scrT[(size_t)p0 * 256 + ch] = lo;
            *(float2*)&V_scrT[(size_t)(p0 + 8) * 256 + ch] = hi;
        }
    }
}

// ---------------------------------------------------------------------------
// Pass 2: softmax over 9 region slots + 9-tap weighted v sum (V transposed)
// ---------------------------------------------------------------------------
__global__ void __launch_bounds__(256) attn_kernel(float* __restrict__ out)
{
    __shared__ float vs[18 * 18 * 36];
    __shared__ float ss[18][18];

    const int h  = blockIdx.z;
    const int bx = blockIdx.x * 16;
    const int by = blockIdx.y * 16;
    const int t  = threadIdx.x;

    for (int i = t; i < 18 * 18; i += 256) {
        int yy = i / 18, xx = i - yy * 18;
        int gy = by + yy - 1, gx = bx + xx - 1;
        float v = 0.f;
        if ((unsigned)gy < HH && (unsigned)gx < WW)
            v = S_scr[h * NPIX + gy * WW + gx];
        ss[yy][xx] = v;
    }
    for (int i = t; i < 18 * 18 * 8; i += 256) {
        int f4 = i & 7; int pi = i >> 3;
        int yy = pi / 18, xx = pi - yy * 18;
        int gy = by + yy - 1, gx = bx + xx - 1;
        float4 v = make_float4(0.f, 0.f, 0.f, 0.f);
        if ((unsigned)gy < HH && (unsigned)gx < WW)
            v = *(const float4*)&V_scrT[(size_t)(gy * WW + gx) * 256 + h * DH + f4 * 4];
        *(float4*)&vs[(yy * 18 + xx) * 36 + f4 * 4] = v;
    }
    __syncthreads();

    const int lx = t & 15, ly = t >> 4;
    const int cy = ly + 1, cx = lx + 1;

    float lg[9];
    #pragma unroll
    for (int s = 0; s < 9; s++) {
        int dy = s / 3 - 1, dx = s % 3 - 1;
        lg[s] = ss[cy + dy][cx + dx] * TEMPER_INV;
    }
    float m = lg[0];
    #pragma unroll
    for (int s = 1; s < 9; s++) m = fmaxf(m, lg[s]);
    float e[9], den = 0.f;
    #pragma unroll
    for (int s = 0; s < 9; s++) { e[s] = __expf(lg[s] - m); den += e[s]; }
    float inv = 1.0f / den;
    #pragma unroll
    for (int s = 0; s < 9; s++) e[s] *= inv;

    float* op = out + (h * DH) * NPIX + (by + ly) * WW + (bx + lx);
    #pragma unroll
    for (int cg = 0; cg < 8; cg++) {
        float4 acc = make_float4(0.f, 0.f, 0.f, 0.f);
        #pragma unroll
        for (int s = 0; s < 9; s++) {
            int dy = s / 3 - 1, dx = s % 3 - 1;
            const float4 tv = *(const float4*)&vs[((cy + dy) * 18 + (cx + dx)) * 36 + cg * 4];
            acc.x += e[s] * tv.x; acc.y += e[s] * tv.y;
            acc.z += e[s] * tv.z; acc.w += e[s] * tv.w;
        }
        op[(cg * 4 + 0) * NPIX] = acc.x;
        op[(cg * 4 + 1) * NPIX] = acc.y;
        op[(cg * 4 + 2) * NPIX] = acc.z;
        op[(cg * 4 + 3) * NPIX] = acc.w;
    }
}

// ---------------------------------------------------------------------------
extern "C" void kernel_launch(void* const* d_in, const int* in_sizes, int n_in,
                              void* d_out, int out_size)
{
    const float* x  = (const float*)d_in[0];
    const float* wq = (const float*)d_in[1];
    const float* wk = (const float*)d_in[2];
    const float* wv = (const float*)d_in[3];
    float* out = (float*)d_out;

    cudaFuncSetAttribute(proj_mma_kernel, cudaFuncAttributeMaxDynamicSharedMemorySize, SMEM_SZ);

    pack_w_kernel<<<(768 * 128 + 255) / 256, 256>>>(wq, wk, wv);
    proj_mma_kernel<<<NPIX / 128, 256, SMEM_SZ>>>(x);

    dim3 g2(WW / 16, HH / 16, NHEAD);
    attn_kernel<<<g2, 256>>>(out);
}

// round 11
// speedup vs baseline: 2.9765x; 1.1796x over previous
#include <cuda_runtime.h>
#include <cuda_fp16.h>
#include <cstdint>

#define HH 192
#define WW 192
#define NPIX (HH*WW)        // 36864
#define CIN 128
#define NHEAD 8
#define DH 32
#define TEMPER_INV (1.0f/16.0f)

// ---------------- global scratch (no cudaMalloc allowed) ----------------
__device__ float V_scrT[(size_t)NPIX * 256];               // [pixel][256 ch]
__device__ float S_scr[NHEAD * NPIX];                      // [head][pixel]
__device__ __align__(16) unsigned short Whi[768 * 128];    // fp16 hi; rows q|k|v
__device__ __align__(16) unsigned short Wlo[768 * 128];    // fp16 residual

// ---------------- smem layout (bytes) ----------------
#define ROWB 272                       // 136 halves per row (128 data + 8 pad)
#define X_H  0                         // x hi plane only (fp16)
#define WB0  34816
#define WB1  104448                    // WB0 + 69632
#define SMEM_SZ 174080                 // WB1 + 69632
#define WPLANE 34816                   // lo-plane offset inside a W buffer

// ---------------- helpers ----------------
__device__ __forceinline__ uint32_t smem_u32(const void* p) {
    uint32_t a;
    asm("{ .reg .u64 t; cvta.to.shared.u64 t, %1; cvt.u32.u64 %0, t; }" : "=r"(a) : "l"(p));
    return a;
}
__device__ __forceinline__ void ldsm4(uint32_t r[4], uint32_t addr) {
    asm volatile("ldmatrix.sync.aligned.m8n8.x4.shared.b16 {%0,%1,%2,%3}, [%4];"
        : "=r"(r[0]), "=r"(r[1]), "=r"(r[2]), "=r"(r[3]) : "r"(addr));
}
__device__ __forceinline__ void mma16816(float d[4], const uint32_t a[4], uint32_t b0, uint32_t b1) {
    asm volatile("mma.sync.aligned.m16n8k16.row.col.f32.f16.f16.f32 "
        "{%0,%1,%2,%3},{%4,%5,%6,%7},{%8,%9},{%0,%1,%2,%3};"
        : "+f"(d[0]), "+f"(d[1]), "+f"(d[2]), "+f"(d[3])
        : "r"(a[0]), "r"(a[1]), "r"(a[2]), "r"(a[3]), "r"(b0), "r"(b1));
}

// ---------------------------------------------------------------------------
// Weight pack: fp16 hi + fp16 residual planes; rows = stacked q|k|v channels
// ---------------------------------------------------------------------------
__global__ void pack_w_kernel(const float* __restrict__ wq,
                              const float* __restrict__ wk,
                              const float* __restrict__ wv)
{
    int i = blockIdx.x * 256 + threadIdx.x;       // 768*128 = 98304
    if (i >= 768 * 128) return;
    int ch = i >> 7, c = i & 127;
    float w;
    if (ch < 256)      w = wq[ch * CIN + c];
    else if (ch < 512) w = wk[(ch - 256) * CIN + c];
    else               w = wv[(ch - 512) * CIN + c];
    __half h = __float2half_rn(w);
    __half l = __float2half_rn(w - __half2float(h));
    Whi[i] = __half_as_ushort(h);
    Wlo[i] = __half_as_ushort(l);
}

// ---------------------------------------------------------------------------
// Pass 1: HMMA projections, fp16 2-term (w_hi + w_lo)·x_hi.
// CTA = 128 pixels, 256 threads (8 warps x 16 pix). Dual-chain interleave.
// ---------------------------------------------------------------------------
__device__ __forceinline__ void copyW(char* smem, int dstoff, int ch0, int t) {
    const float4* hs = (const float4*)Whi;
    const float4* ls = (const float4*)Wlo;
    #pragma unroll
    for (int i = 0; i < 16; i++) {
        int idx = t + i * 256;                // 0..4095 float4
        int plane = idx >> 11;
        int r  = (idx >> 4) & 127;
        int cc = idx & 15;
        const float4* src = plane ? ls : hs;
        float4 v = src[(ch0 + r) * 16 + cc];
        *(float4*)(smem + dstoff + plane * WPLANE + r * ROWB + cc * 16) = v;
    }
}

#define LOADB(bw, bufoff, nt, poff) do {                                        \
    uint32_t bb = sb + (bufoff) + (poff) + ((nt) * 8 + lr) * ROWB + mi * 16;    \
    ldsm4(&(bw)[0], bb); ldsm4(&(bw)[4], bb + 64);                              \
    ldsm4(&(bw)[8], bb + 128); ldsm4(&(bw)[12], bb + 192);                      \
} while (0)

__global__ void __launch_bounds__(256, 1) proj_mma_kernel(const float* __restrict__ x)
{
    extern __shared__ char smem[];
    const uint32_t sb = smem_u32(smem);
    const int t = threadIdx.x;
    const int wid = t >> 5, lane = t & 31;
    const int base = blockIdx.x * 128;

    // ---- x tile: fp16 hi only, stored transposed [pix][k] ----
    #pragma unroll 4
    for (int i = 0; i < 64; i++) {
        int idx = t + i * 256;            // 0..16383
        int c = idx >> 7, p = idx & 127;
        float f = x[c * NPIX + base + p];
        *(unsigned short*)(smem + X_H + p * ROWB + c * 2) =
            __half_as_ushort(__float2half_rn(f));
    }
    __syncthreads();

    // ---- A fragments (held in registers for the whole kernel) ----
    const int mi = lane >> 3, lr = lane & 7;
    const int rowA = wid * 16 + ((mi & 1) << 3) + lr;
    const uint32_t aoff = rowA * ROWB + ((mi >> 1) << 4);
    uint32_t ah[32];
    #pragma unroll
    for (int kt = 0; kt < 8; kt++) ldsm4(&ah[4 * kt], sb + X_H + aoff + kt * 32);
    __syncthreads();

    const int g = lane >> 2;                 // row within warp tile
    const int cq = lane & 3;                 // col quad index
    const int p0 = base + wid * 16 + g;

    // ---- qk phases: heads 0-3 then 4-7 (q and k chains interleaved) ----
    #pragma unroll 1
    for (int h2 = 0; h2 < 2; h2++) {
        copyW(smem, WB0, h2 * 128, t);           // q chunk (hi+lo)
        copyW(smem, WB1, 256 + h2 * 128, t);     // k chunk (hi+lo)
        __syncthreads();

        float sp0 = 0.f, sp1 = 0.f;
        #pragma unroll 1
        for (int nt = 0; nt < 16; nt++) {
            float qd[4] = {0.f, 0.f, 0.f, 0.f};
            float kd[4] = {0.f, 0.f, 0.f, 0.f};
            uint32_t bq[16], bk[16];
            LOADB(bq, WB0, nt, 0);
            LOADB(bk, WB1, nt, 0);
            #pragma unroll
            for (int kt = 0; kt < 8; kt++) {
                mma16816(qd, &ah[4 * kt], bq[2 * kt], bq[2 * kt + 1]);
                mma16816(kd, &ah[4 * kt], bk[2 * kt], bk[2 * kt + 1]);
            }
            LOADB(bq, WB0, nt, WPLANE);
            LOADB(bk, WB1, nt, WPLANE);
            #pragma unroll
            for (int kt = 0; kt < 8; kt++) {
                mma16816(qd, &ah[4 * kt], bq[2 * kt], bq[2 * kt + 1]);
                mma16816(kd, &ah[4 * kt], bk[2 * kt], bk[2 * kt + 1]);
            }
            sp0 += qd[0] * kd[0] + qd[1] * kd[1];
            sp1 += qd[2] * kd[2] + qd[3] * kd[3];
            if ((nt & 3) == 3) {
                float v0 = sp0, v1 = sp1;
                v0 += __shfl_xor_sync(0xffffffffu, v0, 1);
                v0 += __shfl_xor_sync(0xffffffffu, v0, 2);
                v1 += __shfl_xor_sync(0xffffffffu, v1, 1);
                v1 += __shfl_xor_sync(0xffffffffu, v1, 2);
                if (cq == 0) {
                    int head = h2 * 4 + (nt >> 2);
                    S_scr[head * NPIX + p0] = v0;
                    S_scr[head * NPIX + p0 + 8] = v1;
                }
                sp0 = 0.f; sp1 = 0.f;
            }
        }
        __syncthreads();
    }

    // ---- v phase: channels 0-255 (rows 512-767), nt pairs interleaved ----
    copyW(smem, WB0, 512, t);
    copyW(smem, WB1, 640, t);
    __syncthreads();
    #pragma unroll 1
    for (int vc = 0; vc < 2; vc++) {
        const int bufoff = vc ? WB1 : WB0;
        #pragma unroll 1
        for (int nt = 0; nt < 16; nt += 2) {
            float D0[4] = {0.f, 0.f, 0.f, 0.f};
            float D1[4] = {0.f, 0.f, 0.f, 0.f};
            uint32_t b0[16], b1[16];
            LOADB(b0, bufoff, nt, 0);
            LOADB(b1, bufoff, nt + 1, 0);
            #pragma unroll
            for (int kt = 0; kt < 8; kt++) {
                mma16816(D0, &ah[4 * kt], b0[2 * kt], b0[2 * kt + 1]);
                mma16816(D1, &ah[4 * kt], b1[2 * kt], b1[2 * kt + 1]);
            }
            LOADB(b0, bufoff, nt, WPLANE);
            LOADB(b1, bufoff, nt + 1, WPLANE);
            #pragma unroll
            for (int kt = 0; kt < 8; kt++) {
                mma16816(D0, &ah[4 * kt], b0[2 * kt], b0[2 * kt + 1]);
                mma16816(D1, &ah[4 * kt], b1[2 * kt], b1[2 * kt + 1]);
            }
            int ch = vc * 128 + nt * 8 + (cq << 1);
            float2 v;
            v.x = D0[0]; v.y = D0[1];
            *(float2*)&V_scrT[(size_t)p0 * 256 + ch] = v;
            v.x = D0[2]; v.y = D0[3];
            *(float2*)&V_scrT[(size_t)(p0 + 8) * 256 + ch] = v;
            v.x = D1[0]; v.y = D1[1];
            *(float2*)&V_scrT[(size_t)p0 * 256 + ch + 8] = v;
            v.x = D1[2]; v.y = D1[3];
            *(float2*)&V_scrT[(size_t)(p0 + 8) * 256 + ch + 8] = v;
        }
    }
}

// ---------------------------------------------------------------------------
// Pass 2: softmax over 9 region slots + 9-tap weighted v sum (V transposed)
// ---------------------------------------------------------------------------
__global__ void __launch_bounds__(256) attn_kernel(float* __restrict__ out)
{
    __shared__ float vs[18 * 18 * 36];
    __shared__ float ss[18][18];

    const int h  = blockIdx.z;
    const int bx = blockIdx.x * 16;
    const int by = blockIdx.y * 16;
    const int t  = threadIdx.x;

    for (int i = t; i < 18 * 18; i += 256) {
        int yy = i / 18, xx = i - yy * 18;
        int gy = by + yy - 1, gx = bx + xx - 1;
        float v = 0.f;
        if ((unsigned)gy < HH && (unsigned)gx < WW)
            v = S_scr[h * NPIX + gy * WW + gx];
        ss[yy][xx] = v;
    }
    for (int i = t; i < 18 * 18 * 8; i += 256) {
        int f4 = i & 7; int pi = i >> 3;
        int yy = pi / 18, xx = pi - yy * 18;
        int gy = by + yy - 1, gx = bx + xx - 1;
        float4 v = make_float4(0.f, 0.f, 0.f, 0.f);
        if ((unsigned)gy < HH && (unsigned)gx < WW)
            v = *(const float4*)&V_scrT[(size_t)(gy * WW + gx) * 256 + h * DH + f4 * 4];
        *(float4*)&vs[(yy * 18 + xx) * 36 + f4 * 4] = v;
    }
    __syncthreads();

    const int lx = t & 15, ly = t >> 4;
    const int cy = ly + 1, cx = lx + 1;

    float lg[9];
    #pragma unroll
    for (int s = 0; s < 9; s++) {
        int dy = s / 3 - 1, dx = s % 3 - 1;
        lg[s] = ss[cy + dy][cx + dx] * TEMPER_INV;
    }
    float m = lg[0];
    #pragma unroll
    for (int s = 1; s < 9; s++) m = fmaxf(m, lg[s]);
    float e[9], den = 0.f;
    #pragma unroll
    for (int s = 0; s < 9; s++) { e[s] = __expf(lg[s] - m); den += e[s]; }
    float inv = 1.0f / den;
    #pragma unroll
    for (int s = 0; s < 9; s++) e[s] *= inv;

    float* op = out + (h * DH) * NPIX + (by + ly) * WW + (bx + lx);
    #pragma unroll
    for (int cg = 0; cg < 8; cg++) {
        float4 acc = make_float4(0.f, 0.f, 0.f, 0.f);
        #pragma unroll
        for (int s = 0; s < 9; s++) {
            int dy = s / 3 - 1, dx = s % 3 - 1;
            const float4 tv = *(const float4*)&vs[((cy + dy) * 18 + (cx + dx)) * 36 + cg * 4];
            acc.x += e[s] * tv.x; acc.y += e[s] * tv.y;
            acc.z += e[s] * tv.z; acc.w += e[s] * tv.w;
        }
        op[(cg * 4 + 0) * NPIX] = acc.x;
        op[(cg * 4 + 1) * NPIX] = acc.y;
        op[(cg * 4 + 2) * NPIX] = acc.z;
        op[(cg * 4 + 3) * NPIX] = acc.w;
    }
}

// ---------------------------------------------------------------------------
extern "C" void kernel_launch(void* const* d_in, const int* in_sizes, int n_in,
                              void* d_out, int out_size)
{
    const float* x  = (const float*)d_in[0];
    const float* wq = (const float*)d_in[1];
    const float* wk = (const float*)d_in[2];
    const float* wv = (const float*)d_in[3];
    float* out = (float*)d_out;

    cudaFuncSetAttribute(proj_mma_kernel, cudaFuncAttributeMaxDynamicSharedMemorySize, SMEM_SZ);

    pack_w_kernel<<<(768 * 128 + 255) / 256, 256>>>(wq, wk, wv);
    proj_mma_kernel<<<NPIX / 128, 256, SMEM_SZ>>>(x);

    dim3 g2(WW / 16, HH / 16, NHEAD);
    attn_kernel<<<g2, 256>>>(out);
}

// round 15
// speedup vs baseline: 3.5127x; 1.1801x over previous
#include <cuda_runtime.h>
#include <cuda_fp16.h>
#include <cstdint>

#define HH 192
#define WW 192
#define NPIX (HH*WW)        // 36864
#define CIN 128
#define NHEAD 8
#define DH 32
#define TEMPER_INV (1.0f/16.0f)

// ---------------- global scratch (no cudaMalloc allowed) ----------------
__device__ float V_scrT[(size_t)NPIX * 256];               // [pixel][256 ch]
__device__ float S_scr[NHEAD * NPIX];                      // [head][pixel]
__device__ __align__(16) unsigned short Whi[768 * 128];    // fp16 hi; rows q|k|v
__device__ __align__(16) unsigned short Wlo[768 * 128];    // fp16 residual

// ---------------- proj smem layout (bytes) ----------------
#define ROWB 272                       // 136 halves per row (128 data + 8 pad)
#define X_H  0                         // x hi plane (fp16), 128 rows
#define WB0  34816
#define WB1  69632
#define SMEM_SZ 104448                 // 2 CTAs/SM (<= 113664 each)
#define WPLANE 17408                   // lo-plane offset inside a 64-row W buffer

// ---------------- helpers ----------------
__device__ __forceinline__ uint32_t smem_u32(const void* p) {
    uint32_t a;
    asm("{ .reg .u64 t; cvta.to.shared.u64 t, %1; cvt.u32.u64 %0, t; }" : "=r"(a) : "l"(p));
    return a;
}
__device__ __forceinline__ void ldsm4(uint32_t r[4], uint32_t addr) {
    asm volatile("ldmatrix.sync.aligned.m8n8.x4.shared.b16 {%0,%1,%2,%3}, [%4];"
        : "=r"(r[0]), "=r"(r[1]), "=r"(r[2]), "=r"(r[3]) : "r"(addr));
}
__device__ __forceinline__ void mma16816(float d[4], const uint32_t a[4], uint32_t b0, uint32_t b1) {
    asm volatile("mma.sync.aligned.m16n8k16.row.col.f32.f16.f16.f32 "
        "{%0,%1,%2,%3},{%4,%5,%6,%7},{%8,%9},{%0,%1,%2,%3};"
        : "+f"(d[0]), "+f"(d[1]), "+f"(d[2]), "+f"(d[3])
        : "r"(a[0]), "r"(a[1]), "r"(a[2]), "r"(a[3]), "r"(b0), "r"(b1));
}

// ---------------------------------------------------------------------------
// Weight pack: fp16 hi + fp16 residual planes; rows = stacked q|k|v channels
// ---------------------------------------------------------------------------
__global__ void pack_w_kernel(const float* __restrict__ wq,
                              const float* __restrict__ wk,
                              const float* __restrict__ wv)
{
    int i = blockIdx.x * 256 + threadIdx.x;       // 768*128 = 98304
    if (i >= 768 * 128) return;
    int ch = i >> 7, c = i & 127;
    float w;
    if (ch < 256)      w = wq[ch * CIN + c];
    else if (ch < 512) w = wk[(ch - 256) * CIN + c];
    else               w = wv[(ch - 512) * CIN + c];
    __half h = __float2half_rn(w);
    __half l = __float2half_rn(w - __half2float(h));
    Whi[i] = __half_as_ushort(h);
    Wlo[i] = __half_as_ushort(l);
}

// ---------------------------------------------------------------------------
// Pass 1: HMMA projections, fp16 2-term (w_hi + w_lo)·x_hi.
// 64-channel W chunks -> smem 102KB -> 2 CTAs/SM, single wave of 288 CTAs.
// ---------------------------------------------------------------------------
__device__ __forceinline__ void copyW64(char* smem, int dstoff, int ch0, int t) {
    const float4* hs = (const float4*)Whi;
    const float4* ls = (const float4*)Wlo;
    #pragma unroll
    for (int i = 0; i < 8; i++) {
        int idx = t + i * 256;                // 0..2047 float4 (2 planes x 64 rows x 16)
        int plane = idx >> 10;
        int r  = (idx >> 4) & 63;
        int cc = idx & 15;
        const float4* src = plane ? ls : hs;
        float4 v = src[(ch0 + r) * 16 + cc];
        *(float4*)(smem + dstoff + plane * WPLANE + r * ROWB + cc * 16) = v;
    }
}

#define LOADB(bw, bufoff, nt, poff) do {                                        \
    uint32_t bb = sb + (bufoff) + (poff) + ((nt) * 8 + lr) * ROWB + mi * 16;    \
    ldsm4(&(bw)[0], bb); ldsm4(&(bw)[4], bb + 64);                              \
    ldsm4(&(bw)[8], bb + 128); ldsm4(&(bw)[12], bb + 192);                      \
} while (0)

__global__ void __launch_bounds__(256, 2) proj_mma_kernel(const float* __restrict__ x)
{
    extern __shared__ char smem[];
    const uint32_t sb = smem_u32(smem);
    const int t = threadIdx.x;
    const int wid = t >> 5, lane = t & 31;
    const int base = blockIdx.x * 128;

    // ---- x tile: fp16 hi only, stored transposed [pix][k] ----
    #pragma unroll 4
    for (int i = 0; i < 64; i++) {
        int idx = t + i * 256;            // 0..16383
        int c = idx >> 7, p = idx & 127;
        float f = x[c * NPIX + base + p];
        *(unsigned short*)(smem + X_H + p * ROWB + c * 2) =
            __half_as_ushort(__float2half_rn(f));
    }
    __syncthreads();

    // ---- A fragments (held in registers for the whole kernel) ----
    const int mi = lane >> 3, lr = lane & 7;
    const int rowA = wid * 16 + ((mi & 1) << 3) + lr;
    const uint32_t aoff = rowA * ROWB + ((mi >> 1) << 4);
    uint32_t ah[32];
    #pragma unroll
    for (int kt = 0; kt < 8; kt++) ldsm4(&ah[4 * kt], sb + X_H + aoff + kt * 32);
    __syncthreads();

    const int g = lane >> 2;                 // row within warp tile
    const int cq = lane & 3;                 // col quad index
    const int p0 = base + wid * 16 + g;

    // ---- qk phases: 4 x (64 q-ch | 64 k-ch) = 2 heads per phase ----
    #pragma unroll 1
    for (int hp = 0; hp < 4; hp++) {
        copyW64(smem, WB0, hp * 64, t);           // q chunk (hi+lo)
        copyW64(smem, WB1, 256 + hp * 64, t);     // k chunk (hi+lo)
        __syncthreads();

        float sp0 = 0.f, sp1 = 0.f;
        #pragma unroll 1
        for (int nt = 0; nt < 8; nt++) {
            float qd[4] = {0.f, 0.f, 0.f, 0.f};
            float kd[4] = {0.f, 0.f, 0.f, 0.f};
            uint32_t bq[16], bk[16];
            LOADB(bq, WB0, nt, 0);
            LOADB(bk, WB1, nt, 0);
            #pragma unroll
            for (int kt = 0; kt < 8; kt++) {
                mma16816(qd, &ah[4 * kt], bq[2 * kt], bq[2 * kt + 1]);
                mma16816(kd, &ah[4 * kt], bk[2 * kt], bk[2 * kt + 1]);
            }
            LOADB(bq, WB0, nt, WPLANE);
            LOADB(bk, WB1, nt, WPLANE);
            #pragma unroll
            for (int kt = 0; kt < 8; kt++) {
                mma16816(qd, &ah[4 * kt], bq[2 * kt], bq[2 * kt + 1]);
                mma16816(kd, &ah[4 * kt], bk[2 * kt], bk[2 * kt + 1]);
            }
            sp0 += qd[0] * kd[0] + qd[1] * kd[1];
            sp1 += qd[2] * kd[2] + qd[3] * kd[3];
            if ((nt & 3) == 3) {
                float v0 = sp0, v1 = sp1;
                v0 += __shfl_xor_sync(0xffffffffu, v0, 1);
                v0 += __shfl_xor_sync(0xffffffffu, v0, 2);
                v1 += __shfl_xor_sync(0xffffffffu, v1, 1);
                v1 += __shfl_xor_sync(0xffffffffu, v1, 2);
                if (cq == 0) {
                    int head = hp * 2 + (nt >> 2);
                    S_scr[head * NPIX + p0] = v0;
                    S_scr[head * NPIX + p0 + 8] = v1;
                }
                sp0 = 0.f; sp1 = 0.f;
            }
        }
        __syncthreads();
    }

    // ---- v phases: 2 x (two 64-ch chunks), nt pairs dual-chained ----
    #pragma unroll 1
    for (int vp = 0; vp < 2; vp++) {
        copyW64(smem, WB0, 512 + vp * 128, t);
        copyW64(smem, WB1, 512 + vp * 128 + 64, t);
        __syncthreads();
        #pragma unroll 1
        for (int buf = 0; buf < 2; buf++) {
            const int bufoff = buf ? WB1 : WB0;
            #pragma unroll 1
            for (int nt = 0; nt < 8; nt += 2) {
                float D0[4] = {0.f, 0.f, 0.f, 0.f};
                float D1[4] = {0.f, 0.f, 0.f, 0.f};
                uint32_t b0[16], b1[16];
                LOADB(b0, bufoff, nt, 0);
                LOADB(b1, bufoff, nt + 1, 0);
                #pragma unroll
                for (int kt = 0; kt < 8; kt++) {
                    mma16816(D0, &ah[4 * kt], b0[2 * kt], b0[2 * kt + 1]);
                    mma16816(D1, &ah[4 * kt], b1[2 * kt], b1[2 * kt + 1]);
                }
                LOADB(b0, bufoff, nt, WPLANE);
                LOADB(b1, bufoff, nt + 1, WPLANE);
                #pragma unroll
                for (int kt = 0; kt < 8; kt++) {
                    mma16816(D0, &ah[4 * kt], b0[2 * kt], b0[2 * kt + 1]);
                    mma16816(D1, &ah[4 * kt], b1[2 * kt], b1[2 * kt + 1]);
                }
                int ch = vp * 128 + buf * 64 + nt * 8 + (cq << 1);
                float2 v;
                v.x = D0[0]; v.y = D0[1];
                *(float2*)&V_scrT[(size_t)p0 * 256 + ch] = v;
                v.x = D0[2]; v.y = D0[3];
                *(float2*)&V_scrT[(size_t)(p0 + 8) * 256 + ch] = v;
                v.x = D1[0]; v.y = D1[1];
                *(float2*)&V_scrT[(size_t)p0 * 256 + ch + 8] = v;
                v.x = D1[2]; v.y = D1[3];
                *(float2*)&V_scrT[(size_t)(p0 + 8) * 256 + ch + 8] = v;
            }
        }
        __syncthreads();
    }
}

// ---------------------------------------------------------------------------
// Pass 2: softmax + 9-tap weighted v sum. V halo in fp16 smem (stride 40
// halves = 80B: 16B-aligned, conflict-free) -> ~27KB/CTA -> 8 CTAs/SM.
// ---------------------------------------------------------------------------
__global__ void __launch_bounds__(256) attn_kernel(float* __restrict__ out)
{
    __shared__ __half vsh[18 * 18 * 40];
    __shared__ float ss[18][18];

    const int h  = blockIdx.z;
    const int bx = blockIdx.x * 16;
    const int by = blockIdx.y * 16;
    const int t  = threadIdx.x;

    for (int i = t; i < 18 * 18; i += 256) {
        int yy = i / 18, xx = i - yy * 18;
        int gy = by + yy - 1, gx = bx + xx - 1;
        float v = 0.f;
        if ((unsigned)gy < HH && (unsigned)gx < WW)
            v = S_scr[h * NPIX + gy * WW + gx];
        ss[yy][xx] = v;
    }
    for (int i = t; i < 18 * 18 * 8; i += 256) {
        int f4 = i & 7; int pi = i >> 3;
        int yy = pi / 18, xx = pi - yy * 18;
        int gy = by + yy - 1, gx = bx + xx - 1;
        float4 v = make_float4(0.f, 0.f, 0.f, 0.f);
        if ((unsigned)gy < HH && (unsigned)gx < WW)
            v = *(const float4*)&V_scrT[(size_t)(gy * WW + gx) * 256 + h * DH + f4 * 4];
        __half2 a = __floats2half2_rn(v.x, v.y);
        __half2 b = __floats2half2_rn(v.z, v.w);
        uint2 pk;
        pk.x = *(uint32_t*)&a;
        pk.y = *(uint32_t*)&b;
        *(uint2*)&vsh[pi * 40 + f4 * 4] = pk;
    }
    __syncthreads();

    const int lx = t & 15, ly = t >> 4;
    const int cy = ly + 1, cx = lx + 1;

    float lg[9];
    #pragma unroll
    for (int s = 0; s < 9; s++) {
        int dy = s / 3 - 1, dx = s % 3 - 1;
        lg[s] = ss[cy + dy][cx + dx] * TEMPER_INV;
    }
    float m = lg[0];
    #pragma unroll
    for (int s = 1; s < 9; s++) m = fmaxf(m, lg[s]);
    float e[9], den = 0.f;
    #pragma unroll
    for (int s = 0; s < 9; s++) { e[s] = __expf(lg[s] - m); den += e[s]; }
    float inv = 1.0f / den;
    #pragma unroll
    for (int s = 0; s < 9; s++) e[s] *= inv;

    float* op = out + (h * DH) * NPIX + (by + ly) * WW + (bx + lx);
    #pragma unroll
    for (int cg = 0; cg < 4; cg++) {               // 8 channels per group
        float acc[8];
        #pragma unroll
        for (int j = 0; j < 8; j++) acc[j] = 0.f;
        #pragma unroll
        for (int s = 0; s < 9; s++) {
            int dy = s / 3 - 1, dx = s % 3 - 1;
            uint4 hv = *(const uint4*)&vsh[((cy + dy) * 18 + (cx + dx)) * 40 + cg * 8];
            const __half2* h2 = (const __half2*)&hv;
            #pragma unroll
            for (int j = 0; j < 4; j++) {
                float2 f = __half22float2(h2[j]);
                acc[2 * j]     += e[s] * f.x;
                acc[2 * j + 1] += e[s] * f.y;
            }
        }
        #pragma unroll
        for (int j = 0; j < 8; j++)
            op[(cg * 8 + j) * NPIX] = acc[j];
    }
}

// ---------------------------------------------------------------------------
extern "C" void kernel_launch(void* const* d_in, const int* in_sizes, int n_in,
                              void* d_out, int out_size)
{
    const float* x  = (const float*)d_in[0];
    const float* wq = (const float*)d_in[1];
    const float* wk = (const float*)d_in[2];
    const float* wv = (const float*)d_in[3];
    float* out = (float*)d_out;

    cudaFuncSetAttribute(proj_mma_kernel, cudaFuncAttributeMaxDynamicSharedMemorySize, SMEM_SZ);

    pack_w_kernel<<<(768 * 128 + 255) / 256, 256>>>(wq, wk, wv);
    proj_mma_kernel<<<NPIX / 128, 256, SMEM_SZ>>>(x);

    dim3 g2(WW / 16, HH / 16, NHEAD);
    attn_kernel<<<g2, 256>>>(out);
}

// round 16
// speedup vs baseline: 3.7798x; 1.0760x over previous
#include <cuda_runtime.h>
#include <cuda_fp16.h>
#include <cstdint>

#define HH 192
#define WW 192
#define NPIX (HH*WW)        // 36864
#define CIN 128
#define NHEAD 8
#define DH 32
#define TEMPER_INV (1.0f/16.0f)

// ---------------- global scratch (no cudaMalloc allowed) ----------------
__device__ float V_scrT[(size_t)NPIX * 256];               // [pixel][256 ch]
__device__ float S_scr[NHEAD * NPIX];                      // [head][pixel]
__device__ __align__(16) unsigned short Whi[768 * 128];    // fp16 hi; rows q|k|v
__device__ __align__(16) unsigned short Wlo[768 * 128];    // fp16 residual

// ---------------- proj smem layout (bytes) ----------------
#define ROWB 272                       // 136 halves per row (128 data + 8 pad)
#define X_H  0                         // x hi plane (fp16), 128 rows
#define WB0  34816
#define WB1  69632
#define SMEM_SZ 104448                 // 2 CTAs/SM
#define WPLANE 17408                   // lo-plane offset inside a 64-row W buffer

// ---------------- helpers ----------------
__device__ __forceinline__ uint32_t smem_u32(const void* p) {
    uint32_t a;
    asm("{ .reg .u64 t; cvta.to.shared.u64 t, %1; cvt.u32.u64 %0, t; }" : "=r"(a) : "l"(p));
    return a;
}
__device__ __forceinline__ void ldsm4(uint32_t r[4], uint32_t addr) {
    asm volatile("ldmatrix.sync.aligned.m8n8.x4.shared.b16 {%0,%1,%2,%3}, [%4];"
        : "=r"(r[0]), "=r"(r[1]), "=r"(r[2]), "=r"(r[3]) : "r"(addr));
}
__device__ __forceinline__ void mma16816(float d[4], const uint32_t a[4], uint32_t b0, uint32_t b1) {
    asm volatile("mma.sync.aligned.m16n8k16.row.col.f32.f16.f16.f32 "
        "{%0,%1,%2,%3},{%4,%5,%6,%7},{%8,%9},{%0,%1,%2,%3};"
        : "+f"(d[0]), "+f"(d[1]), "+f"(d[2]), "+f"(d[3])
        : "r"(a[0]), "r"(a[1]), "r"(a[2]), "r"(a[3]), "r"(b0), "r"(b1));
}

// ---------------------------------------------------------------------------
// Weight pack: fp16 hi + fp16 residual planes; rows = stacked q|k|v channels
// ---------------------------------------------------------------------------
__global__ void pack_w_kernel(const float* __restrict__ wq,
                              const float* __restrict__ wk,
                              const float* __restrict__ wv)
{
    int i = blockIdx.x * 256 + threadIdx.x;       // 768*128 = 98304
    if (i >= 768 * 128) return;
    int ch = i >> 7, c = i & 127;
    float w;
    if (ch < 256)      w = wq[ch * CIN + c];
    else if (ch < 512) w = wk[(ch - 256) * CIN + c];
    else               w = wv[(ch - 512) * CIN + c];
    __half h = __float2half_rn(w);
    __half l = __float2half_rn(w - __half2float(h));
    Whi[i] = __half_as_ushort(h);
    Wlo[i] = __half_as_ushort(l);
}

// ---------------------------------------------------------------------------
// Pass 1: HMMA projections, fp16 2-term. Warp tiling: 4 M-groups x 2 N-groups.
// Each warp: M=32 (two A tiles in regs) x N=32 -> B smem traffic halved.
// ---------------------------------------------------------------------------
__device__ __forceinline__ void copyW64(char* smem, int dstoff, int ch0, int t) {
    const float4* hs = (const float4*)Whi;
    const float4* ls = (const float4*)Wlo;
    #pragma unroll
    for (int i = 0; i < 8; i++) {
        int idx = t + i * 256;                // 0..2047 float4
        int plane = idx >> 10;
        int r  = (idx >> 4) & 63;
        int cc = idx & 15;
        const float4* src = plane ? ls : hs;
        float4 v = src[(ch0 + r) * 16 + cc];
        *(float4*)(smem + dstoff + plane * WPLANE + r * ROWB + cc * 16) = v;
    }
}

// load one n-tile (8 cols x K=128) of one plane for this warp's N-group
#define LOADB(bw, bufoff, nt, poff) do {                                            \
    uint32_t bb = sb + (bufoff) + (poff) + (ng * 32 + (nt) * 8 + lr) * ROWB + mi * 16; \
    ldsm4(&(bw)[0], bb); ldsm4(&(bw)[4], bb + 64);                                  \
    ldsm4(&(bw)[8], bb + 128); ldsm4(&(bw)[12], bb + 192);                          \
} while (0)

// 16 MMAs: one plane of one n-tile against both A tiles (D[0..3] tile0, D[4..7] tile1)
#define MMA16x2(D, bw) do {                                                         \
    _Pragma("unroll")                                                               \
    for (int kt = 0; kt < 8; kt++) {                                                \
        mma16816(&(D)[0], &ah0[4 * kt], (bw)[2 * kt], (bw)[2 * kt + 1]);            \
        mma16816(&(D)[4], &ah1[4 * kt], (bw)[2 * kt], (bw)[2 * kt + 1]);            \
    }                                                                               \
} while (0)

__global__ void __launch_bounds__(256, 2) proj_mma_kernel(const float* __restrict__ x)
{
    extern __shared__ char smem[];
    const uint32_t sb = smem_u32(smem);
    const int t = threadIdx.x;
    const int wid = t >> 5, lane = t & 31;
    const int base = blockIdx.x * 128;

    // ---- x tile: fp16 hi only, stored transposed [pix][k] ----
    #pragma unroll 4
    for (int i = 0; i < 64; i++) {
        int idx = t + i * 256;            // 0..16383
        int c = idx >> 7, p = idx & 127;
        float f = x[c * NPIX + base + p];
        *(unsigned short*)(smem + X_H + p * ROWB + c * 2) =
            __half_as_ushort(__float2half_rn(f));
    }
    __syncthreads();

    // ---- warp tiling ----
    const int mg = wid >> 1;                 // M-group: rows [mg*32, mg*32+32)
    const int ng = wid & 1;                  // N-group: cols [ng*32, ng*32+32)
    const int mi = lane >> 3, lr = lane & 7;

    // ---- A fragments: two 16-row tiles held in registers ----
    uint32_t ah0[32], ah1[32];
    {
        int r0 = mg * 32 + ((mi & 1) << 3) + lr;
        uint32_t ao0 = r0 * ROWB + ((mi >> 1) << 4);
        uint32_t ao1 = (r0 + 16) * ROWB + ((mi >> 1) << 4);
        #pragma unroll
        for (int kt = 0; kt < 8; kt++) ldsm4(&ah0[4 * kt], sb + X_H + ao0 + kt * 32);
        #pragma unroll
        for (int kt = 0; kt < 8; kt++) ldsm4(&ah1[4 * kt], sb + X_H + ao1 + kt * 32);
    }
    __syncthreads();

    const int g = lane >> 2;                 // row within 16-row tile half
    const int cq = lane & 3;                 // col quad index
    const int p0 = base + mg * 32 + g;       // tile0 row; tile1 = p0+16

    // ---- qk phases: 4 x (64 q-ch | 64 k-ch); warp handles its 32 cols = 1 head ----
    #pragma unroll 1
    for (int hp = 0; hp < 4; hp++) {
        copyW64(smem, WB0, hp * 64, t);           // q chunk (hi+lo)
        copyW64(smem, WB1, 256 + hp * 64, t);     // k chunk (hi+lo)
        __syncthreads();

        float sp0 = 0.f, sp1 = 0.f, sp2 = 0.f, sp3 = 0.f;
        #pragma unroll 1
        for (int nt = 0; nt < 4; nt++) {
            float qd[8] = {0,0,0,0,0,0,0,0};
            float kd[8] = {0,0,0,0,0,0,0,0};
            uint32_t bw[16];
            LOADB(bw, WB0, nt, 0);       MMA16x2(qd, bw);
            LOADB(bw, WB0, nt, WPLANE);  MMA16x2(qd, bw);
            LOADB(bw, WB1, nt, 0);       MMA16x2(kd, bw);
            LOADB(bw, WB1, nt, WPLANE);  MMA16x2(kd, bw);
            sp0 += qd[0] * kd[0] + qd[1] * kd[1];
            sp1 += qd[2] * kd[2] + qd[3] * kd[3];
            sp2 += qd[4] * kd[4] + qd[5] * kd[5];
            sp3 += qd[6] * kd[6] + qd[7] * kd[7];
        }
        // reduce over col quads (4 lanes) -> per-pixel head dot
        sp0 += __shfl_xor_sync(0xffffffffu, sp0, 1);
        sp0 += __shfl_xor_sync(0xffffffffu, sp0, 2);
        sp1 += __shfl_xor_sync(0xffffffffu, sp1, 1);
        sp1 += __shfl_xor_sync(0xffffffffu, sp1, 2);
        sp2 += __shfl_xor_sync(0xffffffffu, sp2, 1);
        sp2 += __shfl_xor_sync(0xffffffffu, sp2, 2);
        sp3 += __shfl_xor_sync(0xffffffffu, sp3, 1);
        sp3 += __shfl_xor_sync(0xffffffffu, sp3, 2);
        if (cq == 0) {
            int head = hp * 2 + ng;
            S_scr[head * NPIX + p0]      = sp0;
            S_scr[head * NPIX + p0 + 8]  = sp1;
            S_scr[head * NPIX + p0 + 16] = sp2;
            S_scr[head * NPIX + p0 + 24] = sp3;
        }
        __syncthreads();
    }

    // ---- v phases: 2 x (two 64-ch chunks); warp covers its 32 cols ----
    #pragma unroll 1
    for (int vp = 0; vp < 2; vp++) {
        copyW64(smem, WB0, 512 + vp * 128, t);
        copyW64(smem, WB1, 512 + vp * 128 + 64, t);
        __syncthreads();
        #pragma unroll 1
        for (int buf = 0; buf < 2; buf++) {
            const int bufoff = buf ? WB1 : WB0;
            #pragma unroll 1
            for (int nt = 0; nt < 4; nt++) {
                float D[8] = {0,0,0,0,0,0,0,0};
                uint32_t bw[16];
                LOADB(bw, bufoff, nt, 0);       MMA16x2(D, bw);
                LOADB(bw, bufoff, nt, WPLANE);  MMA16x2(D, bw);
                int ch = vp * 128 + buf * 64 + ng * 32 + nt * 8 + (cq << 1);
                float2 v;
                v.x = D[0]; v.y = D[1];
                *(float2*)&V_scrT[(size_t)p0 * 256 + ch] = v;
                v.x = D[2]; v.y = D[3];
                *(float2*)&V_scrT[(size_t)(p0 + 8) * 256 + ch] = v;
                v.x = D[4]; v.y = D[5];
                *(float2*)&V_scrT[(size_t)(p0 + 16) * 256 + ch] = v;
                v.x = D[6]; v.y = D[7];
                *(float2*)&V_scrT[(size_t)(p0 + 24) * 256 + ch] = v;
            }
        }
        __syncthreads();
    }
}

// ---------------------------------------------------------------------------
// Pass 2: softmax + 9-tap weighted v sum. V halo in fp16 smem (stride 40
// halves = 80B: 16B-aligned, conflict-free) -> ~27KB/CTA -> 8 CTAs/SM.
// ---------------------------------------------------------------------------
__global__ void __launch_bounds__(256) attn_kernel(float* __restrict__ out)
{
    __shared__ __half vsh[18 * 18 * 40];
    __shared__ float ss[18][18];

    const int h  = blockIdx.z;
    const int bx = blockIdx.x * 16;
    const int by = blockIdx.y * 16;
    const int t  = threadIdx.x;

    for (int i = t; i < 18 * 18; i += 256) {
        int yy = i / 18, xx = i - yy * 18;
        int gy = by + yy - 1, gx = bx + xx - 1;
        float v = 0.f;
        if ((unsigned)gy < HH && (unsigned)gx < WW)
            v = S_scr[h * NPIX + gy * WW + gx];
        ss[yy][xx] = v;
    }
    for (int i = t; i < 18 * 18 * 8; i += 256) {
        int f4 = i & 7; int pi = i >> 3;
        int yy = pi / 18, xx = pi - yy * 18;
        int gy = by + yy - 1, gx = bx + xx - 1;
        float4 v = make_float4(0.f, 0.f, 0.f, 0.f);
        if ((unsigned)gy < HH && (unsigned)gx < WW)
            v = *(const float4*)&V_scrT[(size_t)(gy * WW + gx) * 256 + h * DH + f4 * 4];
        __half2 a = __floats2half2_rn(v.x, v.y);
        __half2 b = __floats2half2_rn(v.z, v.w);
        uint2 pk;
        pk.x = *(uint32_t*)&a;
        pk.y = *(uint32_t*)&b;
        *(uint2*)&vsh[pi * 40 + f4 * 4] = pk;
    }
    __syncthreads();

    const int lx = t & 15, ly = t >> 4;
    const int cy = ly + 1, cx = lx + 1;

    float lg[9];
    #pragma unroll
    for (int s = 0; s < 9; s++) {
        int dy = s / 3 - 1, dx = s % 3 - 1;
        lg[s] = ss[cy + dy][cx + dx] * TEMPER_INV;
    }
    float m = lg[0];
    #pragma unroll
    for (int s = 1; s < 9; s++) m = fmaxf(m, lg[s]);
    float e[9], den = 0.f;
    #pragma unroll
    for (int s = 0; s < 9; s++) { e[s] = __expf(lg[s] - m); den += e[s]; }
    float inv = 1.0f / den;
    #pragma unroll
    for (int s = 0; s < 9; s++) e[s] *= inv;

    float* op = out + (h * DH) * NPIX + (by + ly) * WW + (bx + lx);
    #pragma unroll
    for (int cg = 0; cg < 4; cg++) {               // 8 channels per group
        float acc[8];
        #pragma unroll
        for (int j = 0; j < 8; j++) acc[j] = 0.f;
        #pragma unroll
        for (int s = 0; s < 9; s++) {
            int dy = s / 3 - 1, dx = s % 3 - 1;
            uint4 hv = *(const uint4*)&vsh[((cy + dy) * 18 + (cx + dx)) * 40 + cg * 8];
            const __half2* h2 = (const __half2*)&hv;
            #pragma unroll
            for (int j = 0; j < 4; j++) {
                float2 f = __half22float2(h2[j]);
                acc[2 * j]     += e[s] * f.x;
                acc[2 * j + 1] += e[s] * f.y;
            }
        }
        #pragma unroll
        for (int j = 0; j < 8; j++)
            op[(cg * 8 + j) * NPIX] = acc[j];
    }
}

// ---------------------------------------------------------------------------
extern "C" void kernel_launch(void* const* d_in, const int* in_sizes, int n_in,
                              void* d_out, int out_size)
{
    const float* x  = (const float*)d_in[0];
    const float* wq = (const float*)d_in[1];
    const float* wk = (const float*)d_in[2];
    const float* wv = (const float*)d_in[3];
    float* out = (float*)d_out;

    cudaFuncSetAttribute(proj_mma_kernel, cudaFuncAttributeMaxDynamicSharedMemorySize, SMEM_SZ);

    pack_w_kernel<<<(768 * 128 + 255) / 256, 256>>>(wq, wk, wv);
    proj_mma_kernel<<<NPIX / 128, 256, SMEM_SZ>>>(x);

    dim3 g2(WW / 16, HH / 16, NHEAD);
    attn_kernel<<<g2, 256>>>(out);
}